// round 6
// baseline (speedup 1.0000x reference)
#include <cuda_runtime.h>
#include <cuda_fp16.h>
#include <cstdint>

#define BATCH 4096
#define NA 8
#define ND 11
#define NPOS 3584
#define ATOM 512
#define NS 4096
#define ROWS 32768          // BATCH*NA
#define NTILES 448          // NPOS/8
#define NRB 2048            // ROWS/16 row-blocks
#define EPS 2.5e-3f         // > 2 * (hi-only sim error bound ~9.8e-4)

// A hi fragments (row-major 16x16): g_Afh[rb*32+lane] = {a0,a1,a2,a3}
// B hi fragments (col 16x8):        g_Bfh[nt*32+lane] = {b0,b1}
// Exact normalized vectors for rescore (padded to 12 floats).
__device__ uint4 g_Afh[NRB * 32];
__device__ uint2 g_Bfh[NTILES * 32];
__device__ float g_An[ROWS * 12];
__device__ float g_Bn[NPOS * 12];
__device__ int g_idx[ROWS];

static __device__ __forceinline__ uint32_t h2pack(float x, float y) {
    __half2 h = __halves2half2(__float2half_rn(x), __float2half_rn(y));
    return *(uint32_t*)&h;
}

// ---- Phase 0: normalize (reference op order), fp16-hi fragment pack, exact
//      normalized tables, raw-index passthrough ----
__global__ void prep_kernel(const float* __restrict__ index, const float* __restrict__ positions,
                            float* __restrict__ out_pass) {
    int t = blockIdx.x * blockDim.x + threadIdx.x;
    if (t < NRB * 32) {  // A side
        int rb = t >> 5, lane = t & 31;
        int g = lane >> 2, tig = lane & 3;
        float h[2][16];
#pragma unroll
        for (int rr = 0; rr < 2; rr++) {
            int row = rb * 16 + g + rr * 8;
            const float* ip = index + (size_t)row * ND;
            float v[ND], acc = 0.0f;
#pragma unroll
            for (int d = 0; d < ND; d++) { v[d] = ip[d]; acc = fmaf(v[d], v[d], acc); }
            float nrm = sqrtf(acc);
            if (tig == 0) {
                float* op = out_pass + (size_t)row * ND;
                float* an = g_An + (size_t)row * 12;
#pragma unroll
                for (int d = 0; d < ND; d++) { op[d] = v[d]; an[d] = v[d] / nrm; }
            }
#pragma unroll
            for (int d = 0; d < 16; d++) {
                float f = (d < ND) ? (v[d] / nrm) : 0.0f;
                h[rr][d] = f;
            }
        }
        int k0 = tig * 2;
        g_Afh[t] = make_uint4(h2pack(h[0][k0], h[0][k0 + 1]), h2pack(h[1][k0], h[1][k0 + 1]),
                              h2pack(h[0][k0 + 8], h[0][k0 + 9]), h2pack(h[1][k0 + 8], h[1][k0 + 9]));
    } else if (t < NRB * 32 + NTILES * 32) {  // B side
        int tt = t - NRB * 32;
        int nt = tt >> 5, lane = tt & 31;
        int g = lane >> 2, tig = lane & 3;
        int p = nt * 8 + g;
        const float* pp = positions + (size_t)p * ND;
        float v[ND], acc = 0.0f;
#pragma unroll
        for (int d = 0; d < ND; d++) { v[d] = pp[d]; acc = fmaf(v[d], v[d], acc); }
        float nrm = sqrtf(acc);
        if (tig == 0) {
            float* bn = g_Bn + (size_t)p * 12;
#pragma unroll
            for (int d = 0; d < ND; d++) bn[d] = v[d] / nrm;
        }
        float h[16];
#pragma unroll
        for (int d = 0; d < 16; d++) h[d] = (d < ND) ? (v[d] / nrm) : 0.0f;
        int k0 = tig * 2;
        g_Bfh[tt] = make_uint2(h2pack(h[k0], h[k0 + 1]), h2pack(h[k0 + 8], h[k0 + 9]));
    }
}

static __device__ __forceinline__ void mma16816(float d[4], const uint4& a, uint32_t b0,
                                                uint32_t b1, const float c[4]) {
    asm volatile(
        "mma.sync.aligned.m16n8k16.row.col.f32.f16.f16.f32 "
        "{%0,%1,%2,%3}, {%4,%5,%6,%7}, {%8,%9}, {%10,%11,%12,%13};"
        : "=f"(d[0]), "=f"(d[1]), "=f"(d[2]), "=f"(d[3])
        : "r"(a.x), "r"(a.y), "r"(a.z), "r"(a.w), "r"(b0), "r"(b1),
          "f"(c[0]), "f"(c[1]), "f"(c[2]), "f"(c[3]));
}

static __device__ __forceinline__ void rescore(int row, int pos, unsigned long long& key) {
    const float* a = g_An + (size_t)row * 12;
    const float* b = g_Bn + (size_t)pos * 12;
    float s = a[0] * b[0];
#pragma unroll
    for (int d = 1; d < ND; d++) s = fmaf(a[d], b[d], s);
    unsigned u = __float_as_uint(s);
    u = (u & 0x80000000u) ? ~u : (u | 0x80000000u);
    unsigned long long k = ((unsigned long long)u << 32) | (unsigned)(NPOS - 1 - pos);
    if (k > key) key = k;
}

// ---- Phase 1: coarse hi-only HMMA max sweep + exact fp32 rescore of near-max
// candidates. One warp owns 16 rows; all B hi fragments resident in SMEM. ----
__global__ void __launch_bounds__(512, 1) argmax_kernel(float* __restrict__ out_idx) {
    extern __shared__ uint2 sB[];  // NTILES*32 = 114688 B
    const int tid = threadIdx.x;
    const int lane = tid & 31;
    const int warp = (blockIdx.x << 4) + (tid >> 5);  // row-block id
    const int g = lane >> 2, tig = lane & 3;

    {   // cooperative SMEM fill (uint4-vectorized)
        const uint4* src = (const uint4*)g_Bfh;
        uint4* dst = (uint4*)sB;
        for (int i = tid; i < NTILES * 16; i += 512) dst[i] = src[i];
    }
    const uint4 Ah = g_Afh[warp * 32 + lane];
    __syncthreads();

    const float zc[4] = {0.f, 0.f, 0.f, 0.f};

    // ---- pass 1: coarse per-row max, no index tracking ----
    float best0 = -1e30f, best1 = -1e30f;
#pragma unroll 4
    for (int nt = 0; nt < NTILES; nt++) {
        uint2 B = sB[nt * 32 + lane];
        float dh[4];
        mma16816(dh, Ah, B.x, B.y, zc);
        best0 = fmaxf(best0, fmaxf(dh[0], dh[1]));
        best1 = fmaxf(best1, fmaxf(dh[2], dh[3]));
    }
#pragma unroll
    for (int s = 1; s <= 2; s <<= 1) {
        best0 = fmaxf(best0, __shfl_xor_sync(0xFFFFFFFFu, best0, s));
        best1 = fmaxf(best1, __shfl_xor_sync(0xFFFFFFFFu, best1, s));
    }
    const float T0 = best0 - EPS, T1 = best1 - EPS;
    const int row0 = warp * 16 + g, row1 = row0 + 8;

    // ---- pass 2: find candidates >= T, rescore exactly ----
    unsigned long long k0 = 0ull, k1 = 0ull;
#pragma unroll 4
    for (int nt = 0; nt < NTILES; nt++) {
        uint2 B = sB[nt * 32 + lane];
        float dh[4];
        mma16816(dh, Ah, B.x, B.y, zc);
        if (fmaxf(dh[0], dh[1]) >= T0) {
            int p = nt * 8 + tig * 2;
            if (dh[0] >= T0) rescore(row0, p, k0);
            if (dh[1] >= T0) rescore(row0, p + 1, k0);
        }
        if (fmaxf(dh[2], dh[3]) >= T1) {
            int p = nt * 8 + tig * 2;
            if (dh[2] >= T1) rescore(row1, p, k1);
            if (dh[3] >= T1) rescore(row1, p + 1, k1);
        }
    }

#pragma unroll
    for (int s = 1; s <= 2; s <<= 1) {
        unsigned long long o0 = __shfl_xor_sync(0xFFFFFFFFu, k0, s);
        unsigned long long o1 = __shfl_xor_sync(0xFFFFFFFFu, k1, s);
        if (o0 > k0) k0 = o0;
        if (o1 > k1) k1 = o1;
    }
    if (tig == 0) {
        int i0 = NPOS - 1 - (int)(unsigned)(k0 & 0xFFFFFFFFull);
        int i1 = NPOS - 1 - (int)(unsigned)(k1 & 0xFFFFFFFFull);
        out_idx[row0] = (float)i0;
        out_idx[row1] = (float)i1;
        g_idx[row0] = i0;
        g_idx[row1] = i1;
    }
}

// ---- Phase 2: overlap-add scatter ----
__global__ void scatter_kernel(const float* __restrict__ atoms, float* __restrict__ out) {
    __shared__ __align__(16) float buf[NS];
    int b = blockIdx.x;
    for (int i = threadIdx.x; i < NS; i += blockDim.x) buf[i] = 0.0f;
    __syncthreads();
#pragma unroll
    for (int a = 0; a < NA; a++) {
        int off = g_idx[b * NA + a];
        for (int t = threadIdx.x; t < ATOM; t += blockDim.x)
            buf[off + t] += atoms[a * ATOM + t];
        __syncthreads();
    }
    float4* o = (float4*)(out + (size_t)b * NS);
    const float4* bf = (const float4*)buf;
    for (int i = threadIdx.x; i < NS / 4; i += blockDim.x) o[i] = bf[i];
}

extern "C" void kernel_launch(void* const* d_in, const int* in_sizes, int n_in,
                              void* d_out, int out_size) {
    const float* index = (const float*)d_in[0];      // (4096, 8, 11)
    const float* positions = (const float*)d_in[1];  // (3584, 11)
    const float* atoms = (const float*)d_in[2];      // (8, 512)
    float* out = (float*)d_out;  // [int_index(32768) | output(16777216) | index(360448)]

    prep_kernel<<<(NRB * 32 + NTILES * 32 + 255) / 256, 256>>>(
        index, positions, out + ROWS + (size_t)BATCH * NS);

    const int smem = NTILES * 32 * sizeof(uint2);  // 114688 B
    cudaFuncSetAttribute(argmax_kernel, cudaFuncAttributeMaxDynamicSharedMemorySize, smem);
    argmax_kernel<<<NRB / 16, 512, smem>>>(out);

    scatter_kernel<<<BATCH, 256>>>(atoms, out + ROWS);
}

// round 7
// speedup vs baseline: 1.0496x; 1.0496x over previous
#include <cuda_runtime.h>
#include <cuda_fp16.h>
#include <cstdint>

#define BATCH 4096
#define NA 8
#define ND 11
#define NPOS 3584
#define ATOM 512
#define NS 4096
#define ROWS 32768          // BATCH*NA
#define NTILES 448          // NPOS/8
#define NRB 2048            // ROWS/16 row-blocks
#define CTILES 64           // tiles per SMEM chunk (32 KB)
#define NCH 7               // NTILES/CTILES
#define INV4096 (1.0f/4096.0f)
#define INV2P24 (1.0f/16777216.0f)

__device__ uint4 g_Afh[NRB * 32], g_Afl[NRB * 32];
__device__ uint4 g_Bf[NTILES * 32];
__device__ int g_idx[ROWS];
__device__ int g_dummy;

static __device__ __forceinline__ uint32_t h2pack(float x, float y) {
    __half2 h = __halves2half2(__float2half_rn(x), __float2half_rn(y));
    return *(uint32_t*)&h;
}
static __device__ __forceinline__ uint32_t smem_u32(const void* p) {
    uint32_t a;
    asm("{ .reg .u64 t; cvta.to.shared.u64 t, %1; cvt.u32.u64 %0, t; }" : "=r"(a) : "l"(p));
    return a;
}
#define CP_ASYNC16(smem, gmem) \
    asm volatile("cp.async.cg.shared.global [%0], [%1], 16;" :: "r"(smem), "l"(gmem) : "memory")
#define CP_COMMIT() asm volatile("cp.async.commit_group;" ::: "memory")
#define CP_WAIT(n)  asm volatile("cp.async.wait_group %0;" :: "n"(n) : "memory")

// ---- tiny slot-rotation kernel (also a launch-overhead probe in ncu) ----
__global__ void dummy_kernel() { if (threadIdx.x == 0) g_dummy = 1; }

// ---- Phase 0: normalize (reference op order), fp16 hi/lo split, fragment pack,
//      raw-index passthrough folded in ----
__global__ void prep_kernel(const float* __restrict__ index, const float* __restrict__ positions,
                            float* __restrict__ out_pass) {
    int t = blockIdx.x * blockDim.x + threadIdx.x;
    if (t < NRB * 32) {  // A fragments
        int rb = t >> 5, lane = t & 31;
        int g = lane >> 2, tig = lane & 3;
        float h[2][16], l[2][16];
#pragma unroll
        for (int rr = 0; rr < 2; rr++) {
            int row = rb * 16 + g + rr * 8;
            const float* ip = index + (size_t)row * ND;
            float v[ND], acc = 0.0f;
#pragma unroll
            for (int d = 0; d < ND; d++) { v[d] = ip[d]; acc = fmaf(v[d], v[d], acc); }
            if (tig == 0) {
                float* op = out_pass + (size_t)row * ND;
#pragma unroll
                for (int d = 0; d < ND; d++) op[d] = v[d];
            }
            float nrm = sqrtf(acc);
#pragma unroll
            for (int d = 0; d < 16; d++) {
                float f = (d < ND) ? (v[d] / nrm) : 0.0f;
                float hi = __half2float(__float2half_rn(f));
                h[rr][d] = hi;
                l[rr][d] = (f - hi) * 4096.0f;
            }
        }
        int k0 = tig * 2;
        g_Afh[t] = make_uint4(h2pack(h[0][k0], h[0][k0 + 1]), h2pack(h[1][k0], h[1][k0 + 1]),
                              h2pack(h[0][k0 + 8], h[0][k0 + 9]), h2pack(h[1][k0 + 8], h[1][k0 + 9]));
        g_Afl[t] = make_uint4(h2pack(l[0][k0], l[0][k0 + 1]), h2pack(l[1][k0], l[1][k0 + 1]),
                              h2pack(l[0][k0 + 8], l[0][k0 + 9]), h2pack(l[1][k0 + 8], l[1][k0 + 9]));
    } else if (t < NRB * 32 + NTILES * 32) {  // B fragments
        int tt = t - NRB * 32;
        int nt = tt >> 5, lane = tt & 31;
        int g = lane >> 2, tig = lane & 3;
        int p = nt * 8 + g;
        const float* pp = positions + (size_t)p * ND;
        float v[ND], acc = 0.0f;
#pragma unroll
        for (int d = 0; d < ND; d++) { v[d] = pp[d]; acc = fmaf(v[d], v[d], acc); }
        float nrm = sqrtf(acc);
        float h[16], l[16];
#pragma unroll
        for (int d = 0; d < 16; d++) {
            float f = (d < ND) ? (v[d] / nrm) : 0.0f;
            float hi = __half2float(__float2half_rn(f));
            h[d] = hi;
            l[d] = (f - hi) * 4096.0f;
        }
        int k0 = tig * 2;
        g_Bf[tt] = make_uint4(h2pack(h[k0], h[k0 + 1]), h2pack(h[k0 + 8], h[k0 + 9]),
                              h2pack(l[k0], l[k0 + 1]), h2pack(l[k0 + 8], l[k0 + 9]));
    }
}

static __device__ __forceinline__ void mma16816(float d[4], const uint4& a, uint32_t b0,
                                                uint32_t b1, const float c[4]) {
    asm volatile(
        "mma.sync.aligned.m16n8k16.row.col.f32.f16.f16.f32 "
        "{%0,%1,%2,%3}, {%4,%5,%6,%7}, {%8,%9}, {%10,%11,%12,%13};"
        : "=f"(d[0]), "=f"(d[1]), "=f"(d[2]), "=f"(d[3])
        : "r"(a.x), "r"(a.y), "r"(a.z), "r"(a.w), "r"(b0), "r"(b1),
          "f"(c[0]), "f"(c[1]), "f"(c[2]), "f"(c[3]));
}

// exact 3-limb sims for one tile: s[0],s[1] -> row0 cols p,p+1; s[2],s[3] -> row1
static __device__ __forceinline__ void tile_sims(const uint4& Ah, const uint4& Al,
                                                 const uint4& B, float s[4]) {
    const float zc[4] = {0.f, 0.f, 0.f, 0.f};
    float dh[4], dl[4], dll[4];
    mma16816(dh, Ah, B.x, B.y, zc);
    mma16816(dl, Ah, B.z, B.w, zc);
    mma16816(dl, Al, B.x, B.y, dl);
    mma16816(dll, Al, B.z, B.w, zc);
#pragma unroll
    for (int i = 0; i < 4; i++) s[i] = fmaf(dll[i], INV2P24, fmaf(dl[i], INV4096, dh[i]));
}

// ---- Phase 1: split-fp16 mma GEMM, grouped lazy-argmax epilogue over 2 tiles ----
__global__ void __launch_bounds__(256, 1) argmax_kernel(float* __restrict__ out_idx) {
    extern __shared__ uint4 sB[];  // [2][CTILES*32]
    const int tid = threadIdx.x;
    const int lane = tid & 31;
    const int warp = (blockIdx.x << 3) + (tid >> 5);  // row-block id
    const int g = lane >> 2, tig = lane & 3;
    const uint32_t sb0 = smem_u32(sB);

    const uint4 Ah = g_Afh[warp * 32 + lane];
    const uint4 Al = g_Afl[warp * 32 + lane];

    {   // issue chunk 0
        const uint4* src = g_Bf;
#pragma unroll
        for (int i = 0; i < 8; i++) {
            int idx = tid + i * 256;
            CP_ASYNC16(sb0 + (uint32_t)idx * 16u, src + idx);
        }
        CP_COMMIT();
    }

    float best0 = -1e30f, best1 = -1e30f;
    int bi0 = 0, bi1 = 0;

    for (int c = 0; c < NCH; c++) {
        if (c + 1 < NCH) {
            const uint4* src = g_Bf + (size_t)(c + 1) * (CTILES * 32);
            uint32_t dst = sb0 + (uint32_t)(((c + 1) & 1) * (CTILES * 32) * 16);
#pragma unroll
            for (int i = 0; i < 8; i++) {
                int idx = tid + i * 256;
                CP_ASYNC16(dst + (uint32_t)idx * 16u, src + idx);
            }
            CP_COMMIT();
            CP_WAIT(1);
        } else {
            CP_WAIT(0);
        }
        __syncthreads();

        const uint4* bb = sB + (c & 1) * (CTILES * 32);
        int pbase = c * CTILES * 8 + tig * 2;
#pragma unroll 2
        for (int t = 0; t < CTILES; t += 2) {
            uint4 B0 = bb[t * 32 + lane];
            uint4 B1 = bb[(t + 1) * 32 + lane];
            float sa[4], sb2[4];
            tile_sims(Ah, Al, B0, sa);
            tile_sims(Ah, Al, B1, sb2);
            int p = pbase + t * 8;

            // row0: candidates sa[0],sa[1],sb2[0],sb2[1] at p, p+1, p+8, p+9
            float m0 = fmaxf(fmaxf(sa[0], sa[1]), fmaxf(sb2[0], sb2[1]));
            if (m0 > best0) {  // rare
                best0 = m0;
                bi0 = (m0 == sa[0]) ? p
                    : (m0 == sa[1]) ? p + 1
                    : (m0 == sb2[0]) ? p + 8 : p + 9;
            }
            // row1
            float m1 = fmaxf(fmaxf(sa[2], sa[3]), fmaxf(sb2[2], sb2[3]));
            if (m1 > best1) {  // rare
                best1 = m1;
                bi1 = (m1 == sa[2]) ? p
                    : (m1 == sa[3]) ? p + 1
                    : (m1 == sb2[2]) ? p + 8 : p + 9;
            }
        }
        __syncthreads();
    }

    // reduce across the 4 lanes (tig) sharing each row; tie-break = smaller index
    unsigned u0 = __float_as_uint(best0);
    u0 = (u0 & 0x80000000u) ? ~u0 : (u0 | 0x80000000u);
    unsigned u1 = __float_as_uint(best1);
    u1 = (u1 & 0x80000000u) ? ~u1 : (u1 | 0x80000000u);
    unsigned long long k0 = ((unsigned long long)u0 << 32) | (unsigned)(NPOS - 1 - bi0);
    unsigned long long k1 = ((unsigned long long)u1 << 32) | (unsigned)(NPOS - 1 - bi1);
#pragma unroll
    for (int s = 1; s <= 2; s <<= 1) {
        unsigned long long o0 = __shfl_xor_sync(0xFFFFFFFFu, k0, s);
        unsigned long long o1 = __shfl_xor_sync(0xFFFFFFFFu, k1, s);
        if (o0 > k0) k0 = o0;
        if (o1 > k1) k1 = o1;
    }
    if (tig == 0) {
        int row0 = warp * 16 + g, row1 = row0 + 8;
        int i0 = NPOS - 1 - (int)(unsigned)(k0 & 0xFFFFFFFFull);
        int i1 = NPOS - 1 - (int)(unsigned)(k1 & 0xFFFFFFFFull);
        out_idx[row0] = (float)i0;
        out_idx[row1] = (float)i1;
        g_idx[row0] = i0;
        g_idx[row1] = i1;
    }
}

// ---- Phase 2: overlap-add scatter ----
__global__ void scatter_kernel(const float* __restrict__ atoms, float* __restrict__ out) {
    __shared__ __align__(16) float buf[NS];
    int b = blockIdx.x;
    for (int i = threadIdx.x; i < NS; i += blockDim.x) buf[i] = 0.0f;
    __syncthreads();
#pragma unroll
    for (int a = 0; a < NA; a++) {
        int off = g_idx[b * NA + a];
        for (int t = threadIdx.x; t < ATOM; t += blockDim.x)
            buf[off + t] += atoms[a * ATOM + t];
        __syncthreads();
    }
    float4* o = (float4*)(out + (size_t)b * NS);
    const float4* bf = (const float4*)buf;
    for (int i = threadIdx.x; i < NS / 4; i += blockDim.x) o[i] = bf[i];
}

extern "C" void kernel_launch(void* const* d_in, const int* in_sizes, int n_in,
                              void* d_out, int out_size) {
    const float* index = (const float*)d_in[0];      // (4096, 8, 11)
    const float* positions = (const float*)d_in[1];  // (3584, 11)
    const float* atoms = (const float*)d_in[2];      // (8, 512)
    float* out = (float*)d_out;  // [int_index(32768) | output(16777216) | index(360448)]

    prep_kernel<<<(NRB * 32 + NTILES * 32 + 255) / 256, 256>>>(
        index, positions, out + ROWS + (size_t)BATCH * NS);

    dummy_kernel<<<1, 32>>>();  // rotates the ncu capture slot onto argmax/scatter

    const int smem = 2 * CTILES * 32 * sizeof(uint4);  // 65536 B
    cudaFuncSetAttribute(argmax_kernel, cudaFuncAttributeMaxDynamicSharedMemorySize, smem);
    argmax_kernel<<<NRB / 8, 256, smem>>>(out);

    scatter_kernel<<<BATCH, 256>>>(atoms, out + ROWS);
}

// round 8
// speedup vs baseline: 1.2186x; 1.1610x over previous
#include <cuda_runtime.h>
#include <cuda_fp16.h>
#include <cstdint>

#define BATCH 4096
#define NA 8
#define ND 11
#define NPOS 3584
#define ATOM 512
#define NS 4096
#define ROWS 32768          // BATCH*NA
#define NTILES 448          // NPOS/8
#define NRB 2048            // ROWS/16 row-blocks
#define HTILES 224          // tiles per position-half
#define CTILES 32           // tiles per SMEM chunk (16 KB)
#define NCHH 7              // HTILES/CTILES
#define INV4096 (1.0f/4096.0f)

__device__ uint4 g_Afh[NRB * 32], g_Afl[NRB * 32];
__device__ uint4 g_Bf[NTILES * 32];
__device__ unsigned long long g_key[ROWS];
__device__ int g_dummy;

static __device__ __forceinline__ uint32_t h2pack(float x, float y) {
    __half2 h = __halves2half2(__float2half_rn(x), __float2half_rn(y));
    return *(uint32_t*)&h;
}
static __device__ __forceinline__ uint32_t smem_u32(const void* p) {
    uint32_t a;
    asm("{ .reg .u64 t; cvta.to.shared.u64 t, %1; cvt.u32.u64 %0, t; }" : "=r"(a) : "l"(p));
    return a;
}
#define CP_ASYNC16(smem, gmem) \
    asm volatile("cp.async.cg.shared.global [%0], [%1], 16;" :: "r"(smem), "l"(gmem) : "memory")
#define CP_COMMIT() asm volatile("cp.async.commit_group;" ::: "memory")
#define CP_WAIT(n)  asm volatile("cp.async.wait_group %0;" :: "n"(n) : "memory")

__global__ void dummy_kernel() { if (threadIdx.x == 0) g_dummy = 1; }
__global__ void dummy_kernel2() { if (threadIdx.x == 0) g_dummy = 2; }

// ---- Phase 0: normalize (reference op order), fp16 hi/lo split, fragment pack,
//      raw-index passthrough, zero merge keys ----
__global__ void prep_kernel(const float* __restrict__ index, const float* __restrict__ positions,
                            float* __restrict__ out_pass) {
    int t = blockIdx.x * blockDim.x + threadIdx.x;
    if (t < ROWS) g_key[t] = 0ull;
    if (t < NRB * 32) {  // A fragments
        int rb = t >> 5, lane = t & 31;
        int g = lane >> 2, tig = lane & 3;
        float h[2][16], l[2][16];
#pragma unroll
        for (int rr = 0; rr < 2; rr++) {
            int row = rb * 16 + g + rr * 8;
            const float* ip = index + (size_t)row * ND;
            float v[ND], acc = 0.0f;
#pragma unroll
            for (int d = 0; d < ND; d++) { v[d] = ip[d]; acc = fmaf(v[d], v[d], acc); }
            if (tig == 0) {
                float* op = out_pass + (size_t)row * ND;
#pragma unroll
                for (int d = 0; d < ND; d++) op[d] = v[d];
            }
            float nrm = sqrtf(acc);
#pragma unroll
            for (int d = 0; d < 16; d++) {
                float f = (d < ND) ? (v[d] / nrm) : 0.0f;
                float hi = __half2float(__float2half_rn(f));
                h[rr][d] = hi;
                l[rr][d] = (f - hi) * 4096.0f;
            }
        }
        int k0 = tig * 2;
        g_Afh[t] = make_uint4(h2pack(h[0][k0], h[0][k0 + 1]), h2pack(h[1][k0], h[1][k0 + 1]),
                              h2pack(h[0][k0 + 8], h[0][k0 + 9]), h2pack(h[1][k0 + 8], h[1][k0 + 9]));
        g_Afl[t] = make_uint4(h2pack(l[0][k0], l[0][k0 + 1]), h2pack(l[1][k0], l[1][k0 + 1]),
                              h2pack(l[0][k0 + 8], l[0][k0 + 9]), h2pack(l[1][k0 + 8], l[1][k0 + 9]));
    } else if (t < NRB * 32 + NTILES * 32) {  // B fragments
        int tt = t - NRB * 32;
        int nt = tt >> 5, lane = tt & 31;
        int g = lane >> 2, tig = lane & 3;
        int p = nt * 8 + g;
        const float* pp = positions + (size_t)p * ND;
        float v[ND], acc = 0.0f;
#pragma unroll
        for (int d = 0; d < ND; d++) { v[d] = pp[d]; acc = fmaf(v[d], v[d], acc); }
        float nrm = sqrtf(acc);
        float h[16], l[16];
#pragma unroll
        for (int d = 0; d < 16; d++) {
            float f = (d < ND) ? (v[d] / nrm) : 0.0f;
            float hi = __half2float(__float2half_rn(f));
            h[d] = hi;
            l[d] = (f - hi) * 4096.0f;
        }
        int k0 = tig * 2;
        g_Bf[tt] = make_uint4(h2pack(h[k0], h[k0 + 1]), h2pack(h[k0 + 8], h[k0 + 9]),
                              h2pack(l[k0], l[k0 + 1]), h2pack(l[k0 + 8], l[k0 + 9]));
    }
}

static __device__ __forceinline__ void mma16816(float d[4], const uint4& a, uint32_t b0,
                                                uint32_t b1, const float c[4]) {
    asm volatile(
        "mma.sync.aligned.m16n8k16.row.col.f32.f16.f16.f32 "
        "{%0,%1,%2,%3}, {%4,%5,%6,%7}, {%8,%9}, {%10,%11,%12,%13};"
        : "=f"(d[0]), "=f"(d[1]), "=f"(d[2]), "=f"(d[3])
        : "r"(a.x), "r"(a.y), "r"(a.z), "r"(a.w), "r"(b0), "r"(b1),
          "f"(c[0]), "f"(c[1]), "f"(c[2]), "f"(c[3]));
}

// ---- Phase 1: split-fp16 mma GEMM (2-limb) + streaming argmax.
// blockIdx = (row-block-octet, pos-half). 512 CTAs x 8 warps = 2x warp count
// of the unsplit version; halves merged via atomicMax on packed keys. ----
__global__ void __launch_bounds__(256, 1) argmax_kernel() {
    extern __shared__ uint4 sB[];  // [2][CTILES*32] = 32 KB
    const int tid = threadIdx.x;
    const int lane = tid & 31;
    const int half = blockIdx.x & 1;
    const int warp = ((blockIdx.x >> 1) << 3) + (tid >> 5);  // row-block id
    const int g = lane >> 2, tig = lane & 3;
    const uint32_t sb0 = smem_u32(sB);

    const uint4 Ah = g_Afh[warp * 32 + lane];
    const uint4 Al = g_Afl[warp * 32 + lane];
    const uint4* bsrc = g_Bf + (size_t)half * (HTILES * 32);

    {   // issue chunk 0
#pragma unroll
        for (int i = 0; i < 4; i++) {
            int idx = tid + i * 256;
            CP_ASYNC16(sb0 + (uint32_t)idx * 16u, bsrc + idx);
        }
        CP_COMMIT();
    }

    float best0 = -1e30f, best1 = -1e30f;
    int bi0 = 0, bi1 = 0;
    const float zc[4] = {0.f, 0.f, 0.f, 0.f};

    for (int c = 0; c < NCHH; c++) {
        if (c + 1 < NCHH) {
            const uint4* src = bsrc + (size_t)(c + 1) * (CTILES * 32);
            uint32_t dst = sb0 + (uint32_t)(((c + 1) & 1) * (CTILES * 32) * 16);
#pragma unroll
            for (int i = 0; i < 4; i++) {
                int idx = tid + i * 256;
                CP_ASYNC16(dst + (uint32_t)idx * 16u, src + idx);
            }
            CP_COMMIT();
            CP_WAIT(1);
        } else {
            CP_WAIT(0);
        }
        __syncthreads();

        const uint4* bb = sB + (c & 1) * (CTILES * 32);
        int pbase = half * (HTILES * 8) + c * CTILES * 8 + tig * 2;
#pragma unroll 4
        for (int t = 0; t < CTILES; t++) {
            uint4 B = bb[t * 32 + lane];
            float dh[4], dl[4];
            mma16816(dh, Ah, B.x, B.y, zc);   // Ah*Bh
            mma16816(dl, Ah, B.z, B.w, zc);   // Ah*Bl
            mma16816(dl, Al, B.x, B.y, dl);   // + Al*Bh
            float s0 = fmaf(dl[0], INV4096, dh[0]);
            float s1 = fmaf(dl[1], INV4096, dh[1]);
            float s2 = fmaf(dl[2], INV4096, dh[2]);
            float s3 = fmaf(dl[3], INV4096, dh[3]);

            int p = pbase + t * 8;
            float m0 = fmaxf(s0, s1);
            if (m0 > best0) { best0 = m0; bi0 = (s1 > s0) ? p + 1 : p; }
            float m1 = fmaxf(s2, s3);
            if (m1 > best1) { best1 = m1; bi1 = (s3 > s2) ? p + 1 : p; }
        }
        __syncthreads();
    }

    // reduce across the 4 lanes sharing each row, then merge halves via atomicMax
    unsigned u0 = __float_as_uint(best0);
    u0 = (u0 & 0x80000000u) ? ~u0 : (u0 | 0x80000000u);
    unsigned u1 = __float_as_uint(best1);
    u1 = (u1 & 0x80000000u) ? ~u1 : (u1 | 0x80000000u);
    unsigned long long k0 = ((unsigned long long)u0 << 32) | (unsigned)(NPOS - 1 - bi0);
    unsigned long long k1 = ((unsigned long long)u1 << 32) | (unsigned)(NPOS - 1 - bi1);
#pragma unroll
    for (int s = 1; s <= 2; s <<= 1) {
        unsigned long long o0 = __shfl_xor_sync(0xFFFFFFFFu, k0, s);
        unsigned long long o1 = __shfl_xor_sync(0xFFFFFFFFu, k1, s);
        if (o0 > k0) k0 = o0;
        if (o1 > k1) k1 = o1;
    }
    if (tig == 0) {
        int row0 = warp * 16 + g;
        atomicMax(&g_key[row0], k0);
        atomicMax(&g_key[row0 + 8], k1);
    }
}

// ---- Phase 2: register-direct scatter. 1024 thr/CTA, 4 samples/thread;
// per atom one range test, L1-hit scalar loads, single STG.128. Also decodes
// keys and writes the int_index output section. ----
__global__ void __launch_bounds__(1024) scatter_kernel(const float* __restrict__ atoms,
                                                       float* __restrict__ out) {
    __shared__ int offs[NA];
    const int b = blockIdx.x;
    const int tid = threadIdx.x;
    if (tid < NA) {
        unsigned long long k = g_key[b * NA + tid];
        int idx = NPOS - 1 - (int)(unsigned)(k & 0xFFFFFFFFull);
        offs[tid] = idx;
        out[b * NA + tid] = (float)idx;  // int_index section
    }
    __syncthreads();

    const int s0 = tid * 4;
    float v0 = 0.f, v1 = 0.f, v2 = 0.f, v3 = 0.f;
#pragma unroll
    for (int a = 0; a < NA; a++) {
        int t0 = s0 - offs[a];
        if ((unsigned)(t0 + 3) < (unsigned)(ATOM + 3)) {  // overlap with [0,512)
            const float* ap = atoms + a * ATOM;
            if ((unsigned)t0 < (unsigned)ATOM) v0 += __ldg(ap + t0);
            if ((unsigned)(t0 + 1) < (unsigned)ATOM) v1 += __ldg(ap + t0 + 1);
            if ((unsigned)(t0 + 2) < (unsigned)ATOM) v2 += __ldg(ap + t0 + 2);
            if ((unsigned)(t0 + 3) < (unsigned)ATOM) v3 += __ldg(ap + t0 + 3);
        }
    }
    float4 w = make_float4(v0, v1, v2, v3);
    *(float4*)(out + ROWS + (size_t)b * NS + s0) = w;
}

extern "C" void kernel_launch(void* const* d_in, const int* in_sizes, int n_in,
                              void* d_out, int out_size) {
    const float* index = (const float*)d_in[0];      // (4096, 8, 11)
    const float* positions = (const float*)d_in[1];  // (3584, 11)
    const float* atoms = (const float*)d_in[2];      // (8, 512)
    float* out = (float*)d_out;  // [int_index(32768) | output(16777216) | index(360448)]

    prep_kernel<<<(NRB * 32 + NTILES * 32 + 255) / 256, 256>>>(
        index, positions, out + ROWS + (size_t)BATCH * NS);

    dummy_kernel<<<1, 32>>>();

    const int smem = 2 * CTILES * 32 * sizeof(uint4);  // 32768 B
    cudaFuncSetAttribute(argmax_kernel, cudaFuncAttributeMaxDynamicSharedMemorySize, smem);
    argmax_kernel<<<(NRB / 8) * 2, 256, smem>>>();

    dummy_kernel2<<<1, 32>>>();

    scatter_kernel<<<BATCH, 1024>>>(atoms, out);
}